// round 3
// baseline (speedup 1.0000x reference)
#include <cuda_runtime.h>

// Problem constants (fixed by the dataset)
#define B_    64
#define OBJS_ 2048
#define D_    256
#define K_    2
#define N_    (B_*OBJS_)          // 131072
#define BDK   (B_*D_*K_)          // 32768
#define NK    (N_*K_)             // 262144

#define CPS   8                   // CTAs per scene
#define ROWS_PER_CTA (OBJS_/CPS)  // 256
#define THREADS 256
#define NWARP 8
#define ROWS_PER_WARP (ROWS_PER_CTA/NWARP) // 32
#define NCTA  (B_*CPS)            // 512

typedef unsigned long long u64;

// Scratch (device globals — allocation-free rule). Per-CTA slots, plain stores.
__device__ float g_ctxp [NCTA*D_];     // per-CTA column-sum partials
__device__ float g_featp[NCTA*D_*K_];  // per-CTA pooled-feature partials
__device__ float g_zsump[NCTA*K_];     // per-CTA softmax-denominator partials
__device__ int   g_cnt1[B_];           // phase-1 arrival counters
__device__ int   g_cnt2[B_];           // phase-2 arrival counters (reset by finalK)

// ---- packed f32x2 helpers --------------------------------------------------
__device__ __forceinline__ u64 pack2(float lo, float hi) {
    u64 r; asm("mov.b64 %0,{%1,%2};" : "=l"(r) : "f"(lo), "f"(hi)); return r;
}
__device__ __forceinline__ float2 unpack2(u64 v) {
    float lo, hi; asm("mov.b64 {%0,%1},%2;" : "=f"(lo), "=f"(hi) : "l"(v));
    return make_float2(lo, hi);
}
__device__ __forceinline__ u64 add2(u64 a, u64 b) {
    u64 d; asm("add.rn.f32x2 %0,%1,%2;" : "=l"(d) : "l"(a), "l"(b)); return d;
}
__device__ __forceinline__ u64 fma2(u64 a, u64 b, u64 c) {
    u64 d; asm("fma.rn.f32x2 %0,%1,%2,%3;" : "=l"(d) : "l"(a), "l"(b), "l"(c)); return d;
}
__device__ __forceinline__ u64 abs2(u64 a) {   // clear both sign bits (ALU pipe)
    u64 d; asm("and.b64 %0,%1,0x7FFFFFFF7FFFFFFF;" : "=l"(d) : "l"(a)); return d;
}

// ---------------------------------------------------------------------------
// Fused kernel: pass1 column sums -> scene barrier -> pass2 fused logits/exp/
// pooling (reverse row order for L2 LIFO reuse) -> scene barrier -> write
// normalized attention weights straight to out.
// ---------------------------------------------------------------------------
__global__ __launch_bounds__(THREADS, 3) void fusedK(
    const float* __restrict__ x,
    const float* __restrict__ att,
    const float* __restrict__ scale,
    const float* __restrict__ cb,
    const int*   __restrict__ num_objs,
    float*       __restrict__ out,
    int out_size)
{
    __shared__ __align__(16) float sred[4*D_];       // pass1 reduce (4 KB)
    __shared__ __align__(16) float sctx[D_];         // scene mean context
    __shared__ float sfeat[D_*K_];                   // pass2 feature accum (2 KB)
    __shared__ __align__(8) float sz[ROWS_PER_CTA*K_]; // per-row z values (2 KB)
    __shared__ float sbt[K_];
    __shared__ float szs[K_];

    const int cta   = blockIdx.x;
    const int b     = cta / CPS;
    const int chunk = cta % CPS;
    const int tid   = threadIdx.x;
    const int warp  = tid >> 5, lane = tid & 31;

    // ---------------- pass 1: column sums over this CTA's 256 rows ---------
    {
        const int col4   = tid & 63;
        const int rowgrp = tid >> 6;
        const float4* x4 = (const float4*)x;
        size_t idx = ((size_t)(b*OBJS_ + chunk*ROWS_PER_CTA + rowgrp))*64 + col4;
        float4 acc = {0.f,0.f,0.f,0.f};
        #pragma unroll 8
        for (int i = 0; i < ROWS_PER_CTA/4; i++) {
            float4 v = x4[idx + (size_t)i*256];
            acc.x += v.x; acc.y += v.y; acc.z += v.z; acc.w += v.w;
        }
        *(float4*)&sred[rowgrp*D_ + col4*4] = acc;
    }
    // bias_term (redundant per CTA, trivial)
    if (tid < 64) {
        int k = tid >> 5, l = tid & 31;
        float s = 0.f;
        #pragma unroll
        for (int j = 0; j < 8; j++) s += cb[k*D_ + l + 32*j] * att[l + 32*j];
        #pragma unroll
        for (int m = 16; m; m >>= 1) s += __shfl_xor_sync(0xffffffffu, s, m);
        if (l == 0) sbt[k] = s;
    }
    __syncthreads();
    {
        float p = sred[tid] + sred[D_+tid] + sred[2*D_+tid] + sred[3*D_+tid];
        g_ctxp[(size_t)cta*D_ + tid] = p;
    }
    for (int i = tid; i < D_*K_; i += THREADS) sfeat[i] = 0.f;
    if (tid < K_) szs[tid] = 0.f;

    // ---------------- phase-1 barrier (release: all threads fence) ---------
    __threadfence();
    __syncthreads();
    if (tid == 0) {
        atomicAdd(&g_cnt1[b], 1);
        volatile int* c = &g_cnt1[b];
        while (*c < CPS) __nanosleep(40);
    }
    __syncthreads();

    // scene mean context
    const float invc = 1.f / fmaxf((float)num_objs[b], 1.f);
    {
        float s = 0.f;
        #pragma unroll
        for (int j = 0; j < CPS; j++) s += g_ctxp[(size_t)(b*CPS + j)*D_ + tid];
        sctx[tid] = s * invc;
    }
    __syncthreads();

    // ---------------- pass 2: packed-f32x2 fused logits/exp/pooling --------
    const float bt0 = sbt[0], bt1 = sbt[1];
    const float s0  = scale[0], s1 = scale[1];

    float4 cxa = ((const float4*)sctx)[lane];
    float4 cxb = ((const float4*)sctx)[lane + 32];
    u64 c0 = pack2(cxa.x, cxa.y), c1 = pack2(cxa.z, cxa.w);
    u64 c2 = pack2(cxb.x, cxb.y), c3 = pack2(cxb.z, cxb.w);

    float4 a_a = ((const float4*)att)[lane];
    float4 a_b = ((const float4*)att)[lane + 32];
    // lrelu(t) = 0.6t + 0.4|t|  ->  a*lrelu = (0.6a)*t + (0.4a)*|t|
    u64 a6_0 = pack2(0.6f*a_a.x, 0.6f*a_a.y), a6_1 = pack2(0.6f*a_a.z, 0.6f*a_a.w);
    u64 a6_2 = pack2(0.6f*a_b.x, 0.6f*a_b.y), a6_3 = pack2(0.6f*a_b.z, 0.6f*a_b.w);
    u64 a4_0 = pack2(0.4f*a_a.x, 0.4f*a_a.y), a4_1 = pack2(0.4f*a_a.z, 0.4f*a_a.w);
    u64 a4_2 = pack2(0.4f*a_b.x, 0.4f*a_b.y), a4_3 = pack2(0.4f*a_b.z, 0.4f*a_b.w);

    u64 f0_0=0,f0_1=0,f0_2=0,f0_3=0;   // k=0 pooled features (packed)
    u64 f1_0=0,f1_1=0,f1_2=0,f1_3=0;   // k=1
    float zs0 = 0.f, zs1 = 0.f;

    const int rowbase = b*OBJS_ + chunk*ROWS_PER_CTA + warp*ROWS_PER_WARP;

    // REVERSE order: freshest pass-1 lines re-read first (L2 LIFO reuse)
    #pragma unroll 2
    for (int r = ROWS_PER_WARP-1; r >= 0; --r) {
        int row = rowbase + r;
        const ulonglong2* xr = (const ulonglong2*)(x + (size_t)row * D_);
        ulonglong2 xa = xr[lane];
        ulonglong2 xb = xr[lane + 32];

        u64 t0 = add2(xa.x, c0), t1 = add2(xa.y, c1);
        u64 t2 = add2(xb.x, c2), t3 = add2(xb.y, c3);

        u64 accA = fma2(a6_0, t0, fma2(a4_0, abs2(t0), 0ull));
        accA     = fma2(a6_1, t1, fma2(a4_1, abs2(t1), accA));
        u64 accB = fma2(a6_2, t2, fma2(a4_2, abs2(t2), 0ull));
        accB     = fma2(a6_3, t3, fma2(a4_3, abs2(t3), accB));
        float2 p = unpack2(add2(accA, accB));
        float acc = p.x + p.y;
        #pragma unroll
        for (int m = 16; m; m >>= 1)
            acc += __shfl_xor_sync(0xffffffffu, acc, m);

        float z0 = __expf((acc + bt0) * s0);
        float z1 = __expf((acc + bt1) * s1);
        zs0 += z0; zs1 += z1;
        if (lane == 0)
            *(float2*)&sz[(warp*ROWS_PER_WARP + r)*2] = make_float2(z0, z1);

        u64 zz0 = pack2(z0, z0), zz1 = pack2(z1, z1);
        f0_0 = fma2(xa.x, zz0, f0_0); f0_1 = fma2(xa.y, zz0, f0_1);
        f0_2 = fma2(xb.x, zz0, f0_2); f0_3 = fma2(xb.y, zz0, f0_3);
        f1_0 = fma2(xa.x, zz1, f1_0); f1_1 = fma2(xa.y, zz1, f1_1);
        f1_2 = fma2(xb.x, zz1, f1_2); f1_3 = fma2(xb.y, zz1, f1_3);
    }

    // cross-warp combine via smem atomics (lanes hit distinct addrs in-warp)
    {
        int d0 = 4*lane, d1 = 128 + 4*lane;
        float2 v;
        v = unpack2(f0_0); atomicAdd(&sfeat[(d0+0)*2+0], v.x); atomicAdd(&sfeat[(d0+1)*2+0], v.y);
        v = unpack2(f0_1); atomicAdd(&sfeat[(d0+2)*2+0], v.x); atomicAdd(&sfeat[(d0+3)*2+0], v.y);
        v = unpack2(f0_2); atomicAdd(&sfeat[(d1+0)*2+0], v.x); atomicAdd(&sfeat[(d1+1)*2+0], v.y);
        v = unpack2(f0_3); atomicAdd(&sfeat[(d1+2)*2+0], v.x); atomicAdd(&sfeat[(d1+3)*2+0], v.y);
        v = unpack2(f1_0); atomicAdd(&sfeat[(d0+0)*2+1], v.x); atomicAdd(&sfeat[(d0+1)*2+1], v.y);
        v = unpack2(f1_1); atomicAdd(&sfeat[(d0+2)*2+1], v.x); atomicAdd(&sfeat[(d0+3)*2+1], v.y);
        v = unpack2(f1_2); atomicAdd(&sfeat[(d1+0)*2+1], v.x); atomicAdd(&sfeat[(d1+1)*2+1], v.y);
        v = unpack2(f1_3); atomicAdd(&sfeat[(d1+2)*2+1], v.x); atomicAdd(&sfeat[(d1+3)*2+1], v.y);
    }
    if (lane == 0) { atomicAdd(&szs[0], zs0); atomicAdd(&szs[1], zs1); }
    __syncthreads();

    // store per-CTA partials (plain stores, no pre-zero needed)
    for (int i = tid; i < D_*K_; i += THREADS)
        g_featp[(size_t)cta*(D_*K_) + i] = sfeat[i];
    if (tid < K_) g_zsump[cta*K_ + tid] = szs[tid];

    // ---------------- phase-2 barrier --------------------------------------
    __threadfence();
    __syncthreads();
    if (tid == 0) {
        atomicAdd(&g_cnt2[b], 1);
        volatile int* c = &g_cnt2[b];
        while (*c < CPS) __nanosleep(40);
    }
    __syncthreads();

    // write normalized attention weights straight from smem
    {
        float zt0 = 0.f, zt1 = 0.f;
        #pragma unroll
        for (int j = 0; j < CPS; j++) {
            zt0 += g_zsump[(b*CPS + j)*K_ + 0];
            zt1 += g_zsump[(b*CPS + j)*K_ + 1];
        }
        float inv0 = 1.f/zt0, inv1 = 1.f/zt1;
        if (out_size >= BDK + NK) {
            int outbase = BDK + (b*OBJS_ + chunk*ROWS_PER_CTA)*2;
            for (int i = tid; i < ROWS_PER_CTA*2; i += THREADS)
                out[outbase + i] = sz[i] * ((i & 1) ? inv1 : inv0);
        } else if (out_size == NK) {   // attn-only fallback
            int outbase = (b*OBJS_ + chunk*ROWS_PER_CTA)*2;
            for (int i = tid; i < ROWS_PER_CTA*2; i += THREADS)
                out[outbase + i] = sz[i] * ((i & 1) ? inv1 : inv0);
        }
    }
}

// ---------------------------------------------------------------------------
// Finalize: scene features (reduce 8 partials, normalize) + counter reset.
// One block per scene; thread t handles feature dim d=t (both channels).
// ---------------------------------------------------------------------------
__global__ void finalK(float* __restrict__ out, int out_size)
{
    int b = blockIdx.x, t = threadIdx.x;
    if (b == 0 && t < B_) { g_cnt1[t] = 0; g_cnt2[t] = 0; }

    float2 f = {0.f, 0.f};
    #pragma unroll
    for (int j = 0; j < CPS; j++) {
        const float2* p = (const float2*)&g_featp[(size_t)(b*CPS + j)*(D_*K_)];
        float2 v = p[t];
        f.x += v.x; f.y += v.y;
    }
    float zt0 = 0.f, zt1 = 0.f;
    #pragma unroll
    for (int j = 0; j < CPS; j++) {
        zt0 += g_zsump[(b*CPS + j)*K_ + 0];
        zt1 += g_zsump[(b*CPS + j)*K_ + 1];
    }
    if (out_size >= BDK)   // features live at offset 0 when present
        ((float2*)out)[b*(D_) + t] = make_float2(f.x/zt0, f.y/zt1);
}

// ---------------------------------------------------------------------------
extern "C" void kernel_launch(void* const* d_in, const int* in_sizes, int n_in,
                              void* d_out, int out_size)
{
    const float* x        = (const float*)d_in[0];  // [N, D]
    const int*   num_objs = (const int*)  d_in[1];  // [B]
    const float* att      = (const float*)d_in[2];  // [1, D]
    const float* scale    = (const float*)d_in[3];  // [K, 1]
    const float* cb       = (const float*)d_in[4];  // [K, D]
    float*       out      = (float*)d_out;

    fusedK<<<NCTA, THREADS>>>(x, att, scale, cb, num_objs, out, out_size);
    finalK<<<B_, D_>>>(out, out_size);
}

// round 5
// speedup vs baseline: 1.2466x; 1.2466x over previous
#include <cuda_runtime.h>

// Problem constants (fixed by the dataset)
#define B_    64
#define OBJS_ 2048
#define D_    256
#define K_    2
#define N_    (B_*OBJS_)          // 131072
#define BDK   (B_*D_*K_)          // 32768
#define NK    (N_*K_)             // 262144

#define SPW   32                  // scenes per wave (64 MB, fits L2)
#define WAVES 2
#define CPS   8                   // CTAs per scene
#define NCTA  (SPW*CPS)           // 256 — co-resident at 2 CTAs/SM on 148 SMs
#define ROWS_PER_CTA (OBJS_/CPS)  // 256
#define THREADS 256
#define NWARP 8
#define ROWS_PER_WARP (ROWS_PER_CTA/NWARP) // 32

typedef unsigned long long u64;

// Scratch (device globals — allocation-free rule)
__device__ float g_ctxp [WAVES][NCTA*D_];      // column-sum partials (double-buffered)
__device__ float g_featp[WAVES][NCTA*D_*K_];   // pooled-feature partials
__device__ float g_zsump[WAVES][NCTA*K_];      // softmax-denominator partials
__device__ int   g_bar[4];                     // grid-barrier counters
__device__ int   g_ack;                        // end-of-kernel ack (for reset)

// ---- packed f32x2 helpers --------------------------------------------------
__device__ __forceinline__ u64 pack2(float lo, float hi) {
    u64 r; asm("mov.b64 %0,{%1,%2};" : "=l"(r) : "f"(lo), "f"(hi)); return r;
}
__device__ __forceinline__ float2 unpack2(u64 v) {
    float lo, hi; asm("mov.b64 {%0,%1},%2;" : "=f"(lo), "=f"(hi) : "l"(v));
    return make_float2(lo, hi);
}
__device__ __forceinline__ u64 add2(u64 a, u64 b) {
    u64 d; asm("add.rn.f32x2 %0,%1,%2;" : "=l"(d) : "l"(a), "l"(b)); return d;
}
__device__ __forceinline__ u64 fma2(u64 a, u64 b, u64 c) {
    u64 d; asm("fma.rn.f32x2 %0,%1,%2,%3;" : "=l"(d) : "l"(a), "l"(b), "l"(c)); return d;
}
__device__ __forceinline__ u64 abs2(u64 a) {   // clear both sign bits (ALU pipe)
    u64 d; asm("and.b64 %0,%1,0x7FFFFFFF7FFFFFFF;" : "=l"(d) : "l"(a)); return d;
}

// grid barrier: all NCTA CTAs are co-resident by construction
__device__ __forceinline__ void gridbar(int i, int tid) {
    __threadfence();
    __syncthreads();
    if (tid == 0) {
        atomicAdd(&g_bar[i], 1);
        volatile int* c = &g_bar[i];
        while (*c < NCTA) __nanosleep(32);
    }
    __syncthreads();
}

// ---------------------------------------------------------------------------
__global__ __launch_bounds__(THREADS, 2) void fusedK(
    const float* __restrict__ x,
    const float* __restrict__ att,
    const float* __restrict__ scale,
    const float* __restrict__ cb,
    const int*   __restrict__ num_objs,
    float*       __restrict__ out,
    int out_size)
{
    __shared__ __align__(16) float sred[4*D_];         // pass1 reduce (4 KB)
    __shared__ __align__(16) float sctx[D_];           // scene mean context
    __shared__ float sfeat[D_*K_];                     // pass2 feature accum (2 KB)
    __shared__ __align__(8) float sz[ROWS_PER_CTA*K_]; // per-row z (2 KB)
    __shared__ float sbt[K_];
    __shared__ float szs[K_];

    const int cta   = blockIdx.x;
    const int sIdx  = cta / CPS;         // scene within wave
    const int chunk = cta % CPS;
    const int tid   = threadIdx.x;
    const int warp  = tid >> 5, lane = tid & 31;

    // bias_term (once; persists in smem across waves)
    if (tid < 64) {
        int k = tid >> 5, l = tid & 31;
        float s = 0.f;
        #pragma unroll
        for (int j = 0; j < 8; j++) s += cb[k*D_ + l + 32*j] * att[l + 32*j];
        #pragma unroll
        for (int m = 16; m; m >>= 1) s += __shfl_xor_sync(0xffffffffu, s, m);
        if (l == 0) sbt[k] = s;
    }

    // per-lane invariant att_shared factors for pass2
    float4 a_a = ((const float4*)att)[lane];
    float4 a_b = ((const float4*)att)[lane + 32];
    // lrelu(t) = 0.6t + 0.4|t|  ->  a*lrelu = (0.6a)*t + (0.4a)*|t|
    const u64 a6_0 = pack2(0.6f*a_a.x, 0.6f*a_a.y), a6_1 = pack2(0.6f*a_a.z, 0.6f*a_a.w);
    const u64 a6_2 = pack2(0.6f*a_b.x, 0.6f*a_b.y), a6_3 = pack2(0.6f*a_b.z, 0.6f*a_b.w);
    const u64 a4_0 = pack2(0.4f*a_a.x, 0.4f*a_a.y), a4_1 = pack2(0.4f*a_a.z, 0.4f*a_a.w);
    const u64 a4_2 = pack2(0.4f*a_b.x, 0.4f*a_b.y), a4_3 = pack2(0.4f*a_b.z, 0.4f*a_b.w);

    const bool full_out = (out_size >= BDK + NK);
    const bool attn_only = (!full_out && out_size == NK);

    #pragma unroll 1
    for (int w = 0; w < WAVES; w++) {
        const int b = w*SPW + sIdx;                       // global scene id

        // ============== pass 1: column sums over this CTA's 256 rows =======
        {
            const int col4   = tid & 63;
            const int rowgrp = tid >> 6;
            const float4* x4 = (const float4*)x;
            size_t idx = ((size_t)(b*OBJS_ + chunk*ROWS_PER_CTA + rowgrp))*64 + col4;
            float4 acc = {0.f,0.f,0.f,0.f};
            #pragma unroll 16
            for (int i = 0; i < ROWS_PER_CTA/4; i++) {
                float4 v = x4[idx + (size_t)i*256];       // 4-row stride
                acc.x += v.x; acc.y += v.y; acc.z += v.z; acc.w += v.w;
            }
            *(float4*)&sred[rowgrp*D_ + col4*4] = acc;
        }
        __syncthreads();
        {
            float p = sred[tid] + sred[D_+tid] + sred[2*D_+tid] + sred[3*D_+tid];
            g_ctxp[w][(size_t)cta*D_ + tid] = p;
        }
        for (int i = tid; i < D_*K_; i += THREADS) sfeat[i] = 0.f;
        if (tid < K_) szs[tid] = 0.f;

        gridbar(2*w + 0, tid);   // all pass-1 partials of this wave visible

        // scene mean context
        const float invc = 1.f / fmaxf((float)num_objs[b], 1.f);
        {
            float s = 0.f;
            #pragma unroll
            for (int j = 0; j < CPS; j++)
                s += g_ctxp[w][(size_t)(sIdx*CPS + j)*D_ + tid];
            sctx[tid] = s * invc;
        }
        __syncthreads();

        // ============== pass 2: fused logits + exp + weighted pooling ======
        const float bt0 = sbt[0], bt1 = sbt[1];
        const float s0  = scale[0], s1 = scale[1];

        float4 cxa = ((const float4*)sctx)[lane];
        float4 cxb = ((const float4*)sctx)[lane + 32];
        u64 c0 = pack2(cxa.x, cxa.y), c1 = pack2(cxa.z, cxa.w);
        u64 c2 = pack2(cxb.x, cxb.y), c3 = pack2(cxb.z, cxb.w);

        u64 f0_0=0,f0_1=0,f0_2=0,f0_3=0;   // k=0 pooled features (packed)
        u64 f1_0=0,f1_1=0,f1_2=0,f1_3=0;   // k=1
        float zs0 = 0.f, zs1 = 0.f;

        const int rowbase = b*OBJS_ + chunk*ROWS_PER_CTA + warp*ROWS_PER_WARP;

        // REVERSE order: freshest pass-1 lines re-hit L1/L2 first
        #pragma unroll 4
        for (int r = ROWS_PER_WARP-1; r >= 0; --r) {
            int row = rowbase + r;
            const ulonglong2* xr = (const ulonglong2*)(x + (size_t)row * D_);
            ulonglong2 xa = xr[lane];
            ulonglong2 xb = xr[lane + 32];

            u64 t0 = add2(xa.x, c0), t1 = add2(xa.y, c1);
            u64 t2 = add2(xb.x, c2), t3 = add2(xb.y, c3);

            u64 accA = fma2(a6_0, t0, fma2(a4_0, abs2(t0), 0ull));
            accA     = fma2(a6_1, t1, fma2(a4_1, abs2(t1), accA));
            u64 accB = fma2(a6_2, t2, fma2(a4_2, abs2(t2), 0ull));
            accB     = fma2(a6_3, t3, fma2(a4_3, abs2(t3), accB));
            float2 p = unpack2(add2(accA, accB));
            float acc = p.x + p.y;
            #pragma unroll
            for (int m = 16; m; m >>= 1)
                acc += __shfl_xor_sync(0xffffffffu, acc, m);

            float z0 = __expf((acc + bt0) * s0);
            float z1 = __expf((acc + bt1) * s1);
            zs0 += z0; zs1 += z1;
            if (lane == 0)
                *(float2*)&sz[(warp*ROWS_PER_WARP + r)*2] = make_float2(z0, z1);

            u64 zz0 = pack2(z0, z0), zz1 = pack2(z1, z1);
            f0_0 = fma2(xa.x, zz0, f0_0); f0_1 = fma2(xa.y, zz0, f0_1);
            f0_2 = fma2(xb.x, zz0, f0_2); f0_3 = fma2(xb.y, zz0, f0_3);
            f1_0 = fma2(xa.x, zz1, f1_0); f1_1 = fma2(xa.y, zz1, f1_1);
            f1_2 = fma2(xb.x, zz1, f1_2); f1_3 = fma2(xb.y, zz1, f1_3);
        }

        // cross-warp combine (lanes hit distinct smem addrs within a warp)
        {
            int d0 = 4*lane, d1 = 128 + 4*lane;
            float2 v;
            v = unpack2(f0_0); atomicAdd(&sfeat[(d0+0)*2+0], v.x); atomicAdd(&sfeat[(d0+1)*2+0], v.y);
            v = unpack2(f0_1); atomicAdd(&sfeat[(d0+2)*2+0], v.x); atomicAdd(&sfeat[(d0+3)*2+0], v.y);
            v = unpack2(f0_2); atomicAdd(&sfeat[(d1+0)*2+0], v.x); atomicAdd(&sfeat[(d1+1)*2+0], v.y);
            v = unpack2(f0_3); atomicAdd(&sfeat[(d1+2)*2+0], v.x); atomicAdd(&sfeat[(d1+3)*2+0], v.y);
            v = unpack2(f1_0); atomicAdd(&sfeat[(d0+0)*2+1], v.x); atomicAdd(&sfeat[(d0+1)*2+1], v.y);
            v = unpack2(f1_1); atomicAdd(&sfeat[(d0+2)*2+1], v.x); atomicAdd(&sfeat[(d0+3)*2+1], v.y);
            v = unpack2(f1_2); atomicAdd(&sfeat[(d1+0)*2+1], v.x); atomicAdd(&sfeat[(d1+1)*2+1], v.y);
            v = unpack2(f1_3); atomicAdd(&sfeat[(d1+2)*2+1], v.x); atomicAdd(&sfeat[(d1+3)*2+1], v.y);
        }
        if (lane == 0) { atomicAdd(&szs[0], zs0); atomicAdd(&szs[1], zs1); }
        __syncthreads();

        for (int i = tid; i < D_*K_; i += THREADS)
            g_featp[w][(size_t)cta*(D_*K_) + i] = sfeat[i];
        if (tid < K_) g_zsump[w][cta*K_ + tid] = szs[tid];

        gridbar(2*w + 1, tid);   // all pass-2 partials of this wave visible

        // normalized attention weights for this wave, straight from smem
        if (full_out || attn_only) {
            float zt0 = 0.f, zt1 = 0.f;
            #pragma unroll
            for (int j = 0; j < CPS; j++) {
                zt0 += g_zsump[w][(sIdx*CPS + j)*K_ + 0];
                zt1 += g_zsump[w][(sIdx*CPS + j)*K_ + 1];
            }
            float inv0 = 1.f/zt0, inv1 = 1.f/zt1;
            int base2 = (full_out ? BDK/2 : 0) + b*OBJS_ + chunk*ROWS_PER_CTA;
            float2* o2 = (float2*)out;
            const float2* z2 = (const float2*)sz;
            for (int i = tid; i < ROWS_PER_CTA; i += THREADS) {
                float2 zv = z2[i];
                o2[base2 + i] = make_float2(zv.x*inv0, zv.y*inv1);
            }
        }
    }

    // ---------------- feature finalize (CTAs 0..63, one per scene) ---------
    if (cta < B_ && out_size >= BDK) {
        int fb = cta;                 // scene id
        int fw = fb / SPW, fs = fb % SPW;
        float2 f = {0.f, 0.f};
        #pragma unroll
        for (int j = 0; j < CPS; j++) {
            const float2* p = (const float2*)&g_featp[fw][(size_t)(fs*CPS + j)*(D_*K_)];
            float2 v = p[tid];
            f.x += v.x; f.y += v.y;
        }
        float zt0 = 0.f, zt1 = 0.f;
        #pragma unroll
        for (int j = 0; j < CPS; j++) {
            zt0 += g_zsump[fw][(fs*CPS + j)*K_ + 0];
            zt1 += g_zsump[fw][(fs*CPS + j)*K_ + 1];
        }
        ((float2*)out)[fb*D_ + tid] = make_float2(f.x/zt0, f.y/zt1);
    }

    // ---------------- counter reset (safe: everyone past all spins) --------
    __syncthreads();
    if (tid == 0) {
        atomicAdd(&g_ack, 1);
        if (cta == 0) {
            volatile int* a = &g_ack;
            while (*a < NCTA) __nanosleep(32);
            g_bar[0] = 0; g_bar[1] = 0; g_bar[2] = 0; g_bar[3] = 0;
            g_ack = 0;
        }
    }
}

// ---------------------------------------------------------------------------
extern "C" void kernel_launch(void* const* d_in, const int* in_sizes, int n_in,
                              void* d_out, int out_size)
{
    const float* x        = (const float*)d_in[0];  // [N, D]
    const int*   num_objs = (const int*)  d_in[1];  // [B]
    const float* att      = (const float*)d_in[2];  // [1, D]
    const float* scale    = (const float*)d_in[3];  // [K, 1]
    const float* cb       = (const float*)d_in[4];  // [K, D]
    float*       out      = (float*)d_out;

    fusedK<<<NCTA, THREADS>>>(x, att, scale, cb, num_objs, out, out_size);
}